// round 13
// baseline (speedup 1.0000x reference)
#include <cuda_runtime.h>

#define N_BANDS   224
#define DM        64
#define DS        16
#define MAXROWS   7       // grid = 4*148 = 592 -> 6..7 rows per block
#define NTHREADS  256
#define NGROUPS   4
#define MAXW      32      // max truncated bands
#define CSTRIDE   64
#define ASTRIDE   9
#define LN_EPS    1e-5f

typedef unsigned long long ull;

// ---- row-invariant state: setup kernel -> main kernel ----
__device__ float g_F[(MAXW + 1) * 256];   // [slot][d*4+flavor], +1 pad slot
__device__ float g_k0w[DM], g_k0b[DM];
__device__ int2  g_cw;                    // x = c0, y = W

// ============================ setup kernel ============================
__global__ __launch_bounds__(NTHREADS) void setup_kernel(
    const float* __restrict__ w_in, const float* __restrict__ b_in,
    const float* __restrict__ A_log, const float* __restrict__ Wb,
    const float* __restrict__ Wc, const float* __restrict__ Dvec)
{
    __shared__ alignas(16) float sh_coef[DM * CSTRIDE];
    __shared__ alignas(16) ull   sh_ap[DM * ASTRIDE];
    __shared__ alignas(16) float sh_proj[4][DS];
    __shared__ unsigned sh_emin[NTHREADS / 32];
    __shared__ int sh_W;

    const int tid = threadIdx.x;

    // projections wb = w_in^T Wb etc.
    {
        const int pair = tid >> 2, piece = tid & 3;
        const int s = pair & (DS - 1), which = pair >> 4;
        const float* W = (which < 2) ? Wb : Wc;
        const float* v = (which & 1) ? b_in : w_in;
        const int dd0 = piece * 16;
        float acc = 0.f;
        #pragma unroll 16
        for (int j = 0; j < 16; ++j) acc += v[dd0 + j] * W[(dd0 + j) * DS + s];
        acc += __shfl_xor_sync(0xffffffffu, acc, 1);
        acc += __shfl_xor_sync(0xffffffffu, acc, 2);
        if (piece == 0) sh_proj[which][s] = acc;
    }
    __syncthreads();

    // decays + coefficient algebra (thread: d2 = tid/4, 4 s-values)
    {
        const int d2 = tid >> 2, s0 = (tid & 3) * 4;
        const float wd = w_in[d2], bd = b_in[d2];
        float emin = 1e30f, kw = 0.f, kb = 0.f;
        float a0 = 0.f, a1 = 0.f, a2v = 0.f, a3 = 0.f;
        #pragma unroll
        for (int j = 0; j < 4; ++j) {
            int s = s0 + j;
            float e = expf(A_log[d2 * DS + s]);
            emin = fminf(emin, e);
            float av = expf(-e);
            if (j == 0) a0 = av; else if (j == 1) a1 = av;
            else if (j == 2) a2v = av; else a3 = av;
            float S0 = (1.0f - __powf(av, (float)N_BANDS)) / (1.0f - av);
            float swb = sh_proj[0][s], sbb = sh_proj[1][s];
            float swc = sh_proj[2][s], sbc = sh_proj[3][s];
            float P2 = wd * swb;
            float P1 = wd * sbb + bd * swb;
            float P0 = bd * sbb * S0;
            sh_coef[d2 * CSTRIDE +      s] = P2 * swc;
            sh_coef[d2 * CSTRIDE + 16 + s] = P1 * swc;
            sh_coef[d2 * CSTRIDE + 32 + s] = P2 * sbc;
            sh_coef[d2 * CSTRIDE + 48 + s] = P1 * sbc;
            kw += P0 * swc;
            kb += P0 * sbc;
        }
        {
            float2 v0 = make_float2(a0, a1);
            float2 v1 = make_float2(a2v, a3);
            sh_ap[d2 * ASTRIDE + (s0 >> 1)]     = *reinterpret_cast<ull*>(&v0);
            sh_ap[d2 * ASTRIDE + (s0 >> 1) + 1] = *reinterpret_cast<ull*>(&v1);
        }
        kw += __shfl_xor_sync(0xffffffffu, kw, 1);
        kw += __shfl_xor_sync(0xffffffffu, kw, 2);
        kb += __shfl_xor_sync(0xffffffffu, kb, 1);
        kb += __shfl_xor_sync(0xffffffffu, kb, 2);
        if ((tid & 3) == 0) {
            g_k0w[d2] = kw + Dvec[d2] * wd;
            g_k0b[d2] = kb + Dvec[d2] * bd;
        }
        unsigned em = __reduce_min_sync(0xffffffffu, __float_as_uint(emin));
        if ((tid & 31) == 0) sh_emin[tid >> 5] = em;
    }
    __syncthreads();

    // truncation cutoff: tail rel err <= exp(-12)/(1-a_max) ~ 1e-5
    if (tid == 0) {
        unsigned m = sh_emin[0];
        #pragma unroll
        for (int i = 1; i < NTHREADS / 32; ++i) m = min(m, sh_emin[i]);
        float e_min = __uint_as_float(m);
        int K = (int)ceilf(12.0f / e_min);
        K = (K + 1) & ~1;
        if (K > MAXW) K = MAXW;
        sh_W = K;
        g_cw = make_int2(N_BANDS - K, K);
    }
    __syncthreads();
    const int W = sh_W;

    // F-build: F[slot][tid] = sum_s coef_s * a_s^(223-c), c = c0 + slot
    ull cpk[8], apk[8], pw[8];
    {
        const int df = tid >> 2, fl = tid & 3;
        const float2* cfl = reinterpret_cast<const float2*>(sh_coef + df * CSTRIDE + fl * 16);
        #pragma unroll
        for (int i = 0; i < 8; ++i) {
            float2 cv = cfl[i];
            asm("mov.b64 %0, {%1, %2};" : "=l"(cpk[i]) : "f"(cv.x), "f"(cv.y));
            apk[i] = sh_ap[df * ASTRIDE + i];
            asm("mov.b64 %0, {%1, %1};" : "=l"(pw[i]) : "f"(1.0f));
        }
    }
    #pragma unroll 1
    for (int j = 0; j < W; ++j) {              // newest band first: slot = W-1-j
        ull acc0 = 0ULL, acc1 = 0ULL;
        #pragma unroll
        for (int i = 0; i < 4; ++i) {
            asm("fma.rn.f32x2 %0, %1, %2, %3;"
                : "=l"(acc0) : "l"(cpk[i]), "l"(pw[i]), "l"(acc0));
            asm("fma.rn.f32x2 %0, %1, %2, %3;"
                : "=l"(acc1) : "l"(cpk[4 + i]), "l"(pw[4 + i]), "l"(acc1));
        }
        #pragma unroll
        for (int i = 0; i < 8; ++i) {
            asm("mul.rn.f32x2 %0, %1, %2;" : "=l"(pw[i]) : "l"(pw[i]), "l"(apk[i]));
        }
        asm("add.rn.f32x2 %0, %1, %2;" : "=l"(acc0) : "l"(acc0), "l"(acc1));
        float lo, hi;
        asm("mov.b64 {%0, %1}, %2;" : "=f"(lo), "=f"(hi) : "l"(acc0));
        g_F[(W - 1 - j) * 256 + tid] = lo + hi;
    }
    g_F[W * 256 + tid] = 0.f;   // pad slot for main's prefetch overrun
}

// ============================ main kernel ============================
__global__ __launch_bounds__(NTHREADS, 4) void spectral_main_kernel(
    const float* __restrict__ x,      // (N, 224)
    const float* __restrict__ Wo,     // (64,64)
    const float* __restrict__ bo,
    const float* __restrict__ gamma,
    const float* __restrict__ beta,
    float* __restrict__ out,          // (N, 64)
    int n_total)
{
    __shared__ alignas(16) float sh_x[MAXROWS * N_BANDS + 4];
    __shared__ alignas(16) float sh_out[MAXROWS][DM];
    __shared__ alignas(16) float2 sh_part[MAXROWS][2];

    const int tid = threadIdx.x;
    const int d   = tid & (DM - 1);
    const int nl  = tid >> 6;

    const int row0  = (int)(((long long)blockIdx.x * n_total) / gridDim.x);
    const int row1  = (int)(((long long)(blockIdx.x + 1) * n_total) / gridDim.x);
    const int nrows = row1 - row0;

    const int2 cw = g_cw;
    const int c0 = cw.x, W = cw.y;
    const float bod = bo[d], gd = gamma[d], btd = beta[d];
    const float k0w = g_k0w[d], k0b = g_k0b[d];

    // stage x tile (coalesced float4)
    {
        const float4* xsrc = reinterpret_cast<const float4*>(x + (size_t)row0 * N_BANDS);
        float4* xdst = reinterpret_cast<float4*>(sh_x);
        const int nvec = nrows * (N_BANDS / 4);
        for (int i = tid; i < nvec; i += NTHREADS) xdst[i] = xsrc[i];
    }
    __syncthreads();

    const ulonglong2* __restrict__ Fp = reinterpret_cast<const ulonglong2*>(g_F) + d;

    // row phase: 2 rows per pass; F from gmem (L1-resident), pipelined
    {
        int row = nl;
        #pragma unroll 1
        for (; row + NGROUPS < nrows; row += 2 * NGROUPS) {
            const float* xA = sh_x + row * N_BANDS + c0;
            const float* xB = sh_x + (row + NGROUPS) * N_BANDS + c0;
            ull awA = 0ULL, abA = 0ULL, awB = 0ULL, abB = 0ULL;
            ulonglong2 Fv = __ldg(&Fp[0]);
            #pragma unroll 2
            for (int i = 0; i < W; ++i) {
                ulonglong2 Fn = __ldg(&Fp[(i + 1) * 64]);  // pad slot at i=W-1
                float xa = xA[i], xb = xB[i];
                ull xpa, xpb;
                asm("mov.b64 %0, {%1, %2};" : "=l"(xpa) : "f"(xa * xa), "f"(xa));
                asm("mov.b64 %0, {%1, %2};" : "=l"(xpb) : "f"(xb * xb), "f"(xb));
                asm("fma.rn.f32x2 %0, %1, %2, %3;" : "=l"(awA) : "l"(Fv.x), "l"(xpa), "l"(awA));
                asm("fma.rn.f32x2 %0, %1, %2, %3;" : "=l"(abA) : "l"(Fv.y), "l"(xpa), "l"(abA));
                asm("fma.rn.f32x2 %0, %1, %2, %3;" : "=l"(awB) : "l"(Fv.x), "l"(xpb), "l"(awB));
                asm("fma.rn.f32x2 %0, %1, %2, %3;" : "=l"(abB) : "l"(Fv.y), "l"(xpb), "l"(abB));
                Fv = Fn;
            }
            float l0, h0, l1, h1, l2, h2, l3, h3;
            asm("mov.b64 {%0, %1}, %2;" : "=f"(l0), "=f"(h0) : "l"(awA));
            asm("mov.b64 {%0, %1}, %2;" : "=f"(l1), "=f"(h1) : "l"(abA));
            asm("mov.b64 {%0, %1}, %2;" : "=f"(l2), "=f"(h2) : "l"(awB));
            asm("mov.b64 {%0, %1}, %2;" : "=f"(l3), "=f"(h3) : "l"(abB));
            float xlA = sh_x[row * N_BANDS + N_BANDS - 1];
            float xlB = sh_x[(row + NGROUPS) * N_BANDS + N_BANDS - 1];
            sh_out[row][d]           = xlA * ((l0 + h0) + k0w) + ((l1 + h1) + k0b);
            sh_out[row + NGROUPS][d] = xlB * ((l2 + h2) + k0w) + ((l3 + h3) + k0b);
        }
        if (row < nrows) {
            const float* xA = sh_x + row * N_BANDS + c0;
            ull awA = 0ULL, abA = 0ULL;
            ulonglong2 Fv = __ldg(&Fp[0]);
            #pragma unroll 2
            for (int i = 0; i < W; ++i) {
                ulonglong2 Fn = __ldg(&Fp[(i + 1) * 64]);
                float xa = xA[i];
                ull xpa;
                asm("mov.b64 %0, {%1, %2};" : "=l"(xpa) : "f"(xa * xa), "f"(xa));
                asm("fma.rn.f32x2 %0, %1, %2, %3;" : "=l"(awA) : "l"(Fv.x), "l"(xpa), "l"(awA));
                asm("fma.rn.f32x2 %0, %1, %2, %3;" : "=l"(abA) : "l"(Fv.y), "l"(xpa), "l"(abA));
                Fv = Fn;
            }
            float l0, h0, l1, h1;
            asm("mov.b64 {%0, %1}, %2;" : "=f"(l0), "=f"(h0) : "l"(awA));
            asm("mov.b64 {%0, %1}, %2;" : "=f"(l1), "=f"(h1) : "l"(abA));
            float xlA = sh_x[row * N_BANDS + N_BANDS - 1];
            sh_out[row][d] = xlA * ((l0 + h0) + k0w) + ((l1 + h1) + k0b);
        }
    }
    __syncthreads();

    // out-proj (2 partial sums, low reg pressure) + layernorm partials
    const float4* wrow = reinterpret_cast<const float4*>(Wo + d * DM);
    float zbuf[(MAXROWS + NGROUPS - 1) / NGROUPS];   // <= 2
    #pragma unroll 1
    for (int row = nl, j = 0; row < nrows; row += NGROUPS, ++j) {
        const float4* orow = reinterpret_cast<const float4*>(&sh_out[row][0]);
        float p0 = 0.f, p1 = 0.f;
        #pragma unroll
        for (int i = 0; i < 8; ++i) {
            float4 w0 = wrow[2 * i],     o0 = orow[2 * i];
            float4 w1 = wrow[2 * i + 1], o1 = orow[2 * i + 1];
            p0 += o0.x * w0.x + o0.y * w0.y + o0.z * w0.z + o0.w * w0.w;
            p1 += o1.x * w1.x + o1.y * w1.y + o1.z * w1.z + o1.w * w1.w;
        }
        float zz = bod + p0 + p1;
        zbuf[j] = zz;
        float sum = zz, sq = zz * zz;
        #pragma unroll
        for (int off = 16; off > 0; off >>= 1) {
            sum += __shfl_xor_sync(0xffffffffu, sum, off);
            sq  += __shfl_xor_sync(0xffffffffu, sq,  off);
        }
        if ((tid & 31) == 0) sh_part[row][(tid >> 5) & 1] = make_float2(sum, sq);
    }
    __syncthreads();

    #pragma unroll 1
    for (int row = nl, j = 0; row < nrows; row += NGROUPS, ++j) {
        float2 p0 = sh_part[row][0], p1 = sh_part[row][1];
        float mu  = (p0.x + p1.x) * (1.0f / DM);
        float var = (p0.y + p1.y) * (1.0f / DM) - mu * mu;
        float rn = rsqrtf(var + LN_EPS);
        out[(size_t)(row0 + row) * DM + d] = gd * (zbuf[j] - mu) * rn + btd;
    }
}

extern "C" void kernel_launch(void* const* d_in, const int* in_sizes, int n_in,
                              void* d_out, int out_size) {
    const float* x     = (const float*)d_in[0];
    const float* w_in  = (const float*)d_in[1];
    const float* b_in  = (const float*)d_in[2];
    const float* A_log = (const float*)d_in[3];
    const float* Wb    = (const float*)d_in[4];
    const float* Wc    = (const float*)d_in[5];
    const float* Dv    = (const float*)d_in[6];
    const float* Wo    = (const float*)d_in[7];
    const float* bo    = (const float*)d_in[8];
    const float* gm    = (const float*)d_in[9];
    const float* bt    = (const float*)d_in[10];
    float* out = (float*)d_out;

    int N = in_sizes[0] / N_BANDS;          // 4096
    int grid = 4 * 148;                     // 592 -> 6..7 rows per block
    if ((N + grid - 1) / grid > MAXROWS) grid = (N + MAXROWS - 1) / MAXROWS;

    setup_kernel<<<1, NTHREADS>>>(w_in, b_in, A_log, Wb, Wc, Dv);
    spectral_main_kernel<<<grid, NTHREADS>>>(x, Wo, bo, gm, bt, out, N);
}